// round 4
// baseline (speedup 1.0000x reference)
#include <cuda_runtime.h>
#include <cstdint>

// BlockDecomposition RGCN layer, GB300 sm_103a — relation-sorted scatter version.
// out[n] = mask[n]*(xb[n] @ W[16]) + sum_{edges, both dirs} w*(xb[s] @ W[r]) -> t

#define NUM_BLOCKS 32
#define BS 4
#define DIM 128
#define BLK_STRIDE 512       // floats per relation
#define NUM_REL 16
#define NUM_REL_TOT 17
#define REL_CAP 160000       // worst-case: all edges one relation
#define BLOCKS_PER_REL 64
#define WARPS_PER_REL (BLOCKS_PER_REL * 8)

// Transposed weights: W'[r][i][b][j] = blocks[r][b][i][j] (warp-contiguous reads)
__device__ float g_wt[NUM_REL_TOT * BLK_STRIDE];
// Relation buckets: packed edge records {src, tgt, w_bits, 0}
__device__ int4  g_rec[NUM_REL * (size_t)REL_CAP];
__device__ int   g_cnt[NUM_REL];

__device__ __forceinline__ void red_add_v4(float* p, float4 v) {
    asm volatile("red.global.add.v4.f32 [%0], {%1, %2, %3, %4};"
                 :: "l"(p), "f"(v.x), "f"(v.y), "f"(v.z), "f"(v.w)
                 : "memory");
}

__device__ __forceinline__ float4 block_mm(float4 xv, float4 w0, float4 w1, float4 w2, float4 w3) {
    float4 m;
    m.x = fmaf(xv.x, w0.x, fmaf(xv.y, w1.x, fmaf(xv.z, w2.x, xv.w * w3.x)));
    m.y = fmaf(xv.x, w0.y, fmaf(xv.y, w1.y, fmaf(xv.z, w2.y, xv.w * w3.y)));
    m.z = fmaf(xv.x, w0.z, fmaf(xv.y, w1.z, fmaf(xv.z, w2.z, xv.w * w3.z)));
    m.w = fmaf(xv.x, w0.w, fmaf(xv.y, w1.w, fmaf(xv.z, w2.w, xv.w * w3.w)));
    return m;
}

// Kernel 1: self-loop transform + mask (initializes out); also transposes
// weights into g_wt (blocks 0..16) and zeroes bucket cursors (block 17).
__global__ void __launch_bounds__(256) self_loop_kernel(
    const float* __restrict__ x,
    const int* __restrict__ keep_mask,
    const float* __restrict__ blocks,
    float* __restrict__ out,
    int n_nodes)
{
    if (blockIdx.x < NUM_REL_TOT) {
        int r = blockIdx.x;
        #pragma unroll
        for (int k = 0; k < 2; k++) {
            int idx = threadIdx.x + k * 256;        // 0..511
            int b = idx >> 4;
            int i = (idx >> 2) & 3;
            int j = idx & 3;
            g_wt[r * BLK_STRIDE + i * 128 + b * 4 + j] = blocks[r * BLK_STRIDE + idx];
        }
    } else if (blockIdx.x == NUM_REL_TOT && threadIdx.x < NUM_REL) {
        g_cnt[threadIdx.x] = 0;
    }

    int warp = (blockIdx.x * blockDim.x + threadIdx.x) >> 5;
    int lane = threadIdx.x & 31;
    if (warp >= n_nodes) return;

    const float4 xv = *reinterpret_cast<const float4*>(x + (size_t)warp * DIM + lane * BS);
    const float4* wp = reinterpret_cast<const float4*>(blocks + 16 * BLK_STRIDE + lane * 16);
    float4 w0 = wp[0], w1 = wp[1], w2 = wp[2], w3 = wp[3];

    float4 m = block_mm(xv, w0, w1, w2, w3);
    if (keep_mask[warp] == 0) { m.x = 0.f; m.y = 0.f; m.z = 0.f; m.w = 0.f; }
    *reinterpret_cast<float4*>(out + (size_t)warp * DIM + lane * BS) = m;
}

// Kernel 2: bucket edges by relation (block-aggregated atomics, no scan).
__global__ void __launch_bounds__(256) build_kernel(
    const int* __restrict__ src,
    const int* __restrict__ tgt,
    const int* __restrict__ etype,
    const float* __restrict__ eweight,
    int n_edges)
{
    __shared__ int s_cnt[NUM_REL];
    __shared__ int s_base[NUM_REL];
    if (threadIdx.x < NUM_REL) s_cnt[threadIdx.x] = 0;
    __syncthreads();

    int e = blockIdx.x * 256 + threadIdx.x;
    int s = 0, t = 0, r = 0, local = 0;
    float w = 0.f;
    bool valid = (e < n_edges);
    if (valid) {
        s = src[e]; t = tgt[e]; r = etype[e]; w = eweight[e];
        local = atomicAdd(&s_cnt[r], 1);
    }
    __syncthreads();
    if (threadIdx.x < NUM_REL && s_cnt[threadIdx.x] > 0)
        s_base[threadIdx.x] = atomicAdd(&g_cnt[threadIdx.x], s_cnt[threadIdx.x]);
    __syncthreads();
    if (valid) {
        int pos = s_base[r] + local;
        if (pos < REL_CAP)
            g_rec[(size_t)r * REL_CAP + pos] = make_int4(s, t, __float_as_int(w), 0);
    }
}

// Kernel 3: sorted edge processing. Each warp serves one relation; weights
// live in registers across all its edges. Both directions per record.
__global__ void __launch_bounds__(256) edge_sorted_kernel(
    const float* __restrict__ x,
    float* __restrict__ out)
{
    int rel   = blockIdx.x / BLOCKS_PER_REL;
    int wrank = ((blockIdx.x % BLOCKS_PER_REL) * 256 + threadIdx.x) >> 5;
    int lane  = threadIdx.x & 31;

    int cnt = g_cnt[rel];
    if (cnt > REL_CAP) cnt = REL_CAP;

    // per-warp register weights for this relation (coalesced from transposed table)
    const float* wbase = g_wt + (size_t)rel * BLK_STRIDE + lane * 4;
    float4 w0 = *reinterpret_cast<const float4*>(wbase);
    float4 w1 = *reinterpret_cast<const float4*>(wbase + 128);
    float4 w2 = *reinterpret_cast<const float4*>(wbase + 256);
    float4 w3 = *reinterpret_cast<const float4*>(wbase + 384);

    const int4* recs = g_rec + (size_t)rel * REL_CAP;

    for (int i = wrank; i < cnt; i += WARPS_PER_REL) {
        int4 rec = recs[i];                       // broadcast (same addr all lanes)
        int s = rec.x, t = rec.y;
        float w = __int_as_float(rec.z);

        float4 xs = *reinterpret_cast<const float4*>(x + (size_t)s * DIM + lane * BS);
        float4 xt = *reinterpret_cast<const float4*>(x + (size_t)t * DIM + lane * BS);

        float4 m1 = block_mm(xs, w0, w1, w2, w3);
        m1.x *= w; m1.y *= w; m1.z *= w; m1.w *= w;
        float4 m2 = block_mm(xt, w0, w1, w2, w3);
        m2.x *= w; m2.y *= w; m2.z *= w; m2.w *= w;

        red_add_v4(out + (size_t)t * DIM + lane * BS, m1);
        red_add_v4(out + (size_t)s * DIM + lane * BS, m2);
    }
}

extern "C" void kernel_launch(void* const* d_in, const int* in_sizes, int n_in,
                              void* d_out, int out_size)
{
    const float* x      = (const float*)d_in[0];
    const int*   mask   = (const int*)d_in[1];
    const int*   src    = (const int*)d_in[2];
    const int*   tgt    = (const int*)d_in[3];
    const int*   etype  = (const int*)d_in[4];
    const float* ew     = (const float*)d_in[5];
    const float* blocks = (const float*)d_in[6];
    float*       out    = (float*)d_out;

    int n_nodes = in_sizes[0] / DIM;
    int n_edges = in_sizes[2];

    // K1: out init (self-loop+mask), weight transpose, cursor reset
    {
        int total_threads = n_nodes * 32;
        int grid = (total_threads + 255) / 256;
        self_loop_kernel<<<grid, 256>>>(x, mask, blocks, out, n_nodes);
    }
    // K2: bucket edges by relation
    {
        int grid = (n_edges + 255) / 256;
        build_kernel<<<grid, 256>>>(src, tgt, etype, ew, n_edges);
    }
    // K3: relation-sorted edge messages with register-resident weights
    {
        edge_sorted_kernel<<<NUM_REL * BLOCKS_PER_REL, 256>>>(x, out);
    }
}

// round 6
// speedup vs baseline: 2.0420x; 2.0420x over previous
#include <cuda_runtime.h>
#include <cstdint>

// BlockDecomposition RGCN layer, GB300 sm_103a
// out[n] = mask[n]*(xb[n] @ W[16]) + sum_{edges, both dirs} w*(xb[s] @ W[r]) -> t
// xb: (N, 32, 4); blocks: (17, 32, 4, 4)

#define NUM_BLOCKS 32
#define BS 4
#define DIM 128
#define BLK_STRIDE 512       // floats per relation
#define NUM_REL_TOT 17

// Transposed weights: W'[r][i][b][j] = blocks[r][b][i][j]
// -> warp (lane=b) reads each i-row as one contiguous 512B span.
__device__ float g_wt[NUM_REL_TOT * BLK_STRIDE];

__device__ __forceinline__ void red_add_v4(float* p, float4 v) {
    asm volatile("red.global.add.v4.f32 [%0], {%1, %2, %3, %4};"
                 :: "l"(p), "f"(v.x), "f"(v.y), "f"(v.z), "f"(v.w)
                 : "memory");
}

__device__ __forceinline__ float4 block_mm(float4 xv, float4 w0, float4 w1, float4 w2, float4 w3) {
    float4 m;
    m.x = fmaf(xv.x, w0.x, fmaf(xv.y, w1.x, fmaf(xv.z, w2.x, xv.w * w3.x)));
    m.y = fmaf(xv.x, w0.y, fmaf(xv.y, w1.y, fmaf(xv.z, w2.y, xv.w * w3.y)));
    m.z = fmaf(xv.x, w0.z, fmaf(xv.y, w1.z, fmaf(xv.z, w2.z, xv.w * w3.z)));
    m.w = fmaf(xv.x, w0.w, fmaf(xv.y, w1.w, fmaf(xv.z, w2.w, xv.w * w3.w)));
    return m;
}

// Kernel 1: self-loop transform + mask (initializes out). Weights for
// relation 16 staged through smem (transposed, conflict-free LDS).
// Blocks 0..16 also transpose all relations' weights into g_wt for kernel 2.
__global__ void __launch_bounds__(256) self_loop_kernel(
    const float* __restrict__ x,
    const int* __restrict__ keep_mask,   // bool materialized as int32
    const float* __restrict__ blocks,
    float* __restrict__ out,
    int n_nodes)
{
    __shared__ float s_w[BLK_STRIDE];

    // transpose g_wt (one relation per block, first 17 blocks)
    if (blockIdx.x < NUM_REL_TOT) {
        int r = blockIdx.x;
        #pragma unroll
        for (int k = 0; k < 2; k++) {
            int idx = threadIdx.x + k * 256;     // 0..511
            int b = idx >> 4, i = (idx >> 2) & 3, j = idx & 3;
            g_wt[r * BLK_STRIDE + i * 128 + b * 4 + j] = blocks[r * BLK_STRIDE + idx];
        }
    }

    // stage self-loop weights (relation 16), transposed, into smem
    #pragma unroll
    for (int k = 0; k < 2; k++) {
        int idx = threadIdx.x + k * 256;
        int b = idx >> 4, i = (idx >> 2) & 3, j = idx & 3;
        s_w[i * 128 + b * 4 + j] = blocks[16 * BLK_STRIDE + idx];
    }
    __syncthreads();

    int warp = (blockIdx.x * blockDim.x + threadIdx.x) >> 5;
    int lane = threadIdx.x & 31;
    if (warp >= n_nodes) return;

    const float4 xv = *reinterpret_cast<const float4*>(x + (size_t)warp * DIM + lane * BS);
    const float* wb = s_w + lane * 4;
    float4 w0 = *reinterpret_cast<const float4*>(wb);
    float4 w1 = *reinterpret_cast<const float4*>(wb + 128);
    float4 w2 = *reinterpret_cast<const float4*>(wb + 256);
    float4 w3 = *reinterpret_cast<const float4*>(wb + 384);

    float4 m = block_mm(xv, w0, w1, w2, w3);
    if (keep_mask[warp] == 0) { m.x = 0.f; m.y = 0.f; m.z = 0.f; m.w = 0.f; }
    *reinterpret_cast<float4*>(out + (size_t)warp * DIM + lane * BS) = m;
}

// Kernel 2: TWO edges per warp (e, e+half), both directions each.
// All four x gathers issue before consumption -> 4 outstanding L2 loads/warp.
__global__ void __launch_bounds__(256) edge_kernel(
    const float* __restrict__ x,
    const int* __restrict__ src,
    const int* __restrict__ tgt,
    const int* __restrict__ etype,
    const float* __restrict__ eweight,
    float* __restrict__ out,
    int n_edges, int half)
{
    int warp = (blockIdx.x * blockDim.x + threadIdx.x) >> 5;
    int lane = threadIdx.x & 31;
    if (warp >= half) return;

    int e0 = warp;
    int e1 = warp + half;
    bool has1 = (e1 < n_edges);

    int s0 = src[e0], t0 = tgt[e0], r0 = etype[e0];
    float wgt0 = eweight[e0];
    int s1 = s0, t1 = t0, r1 = r0;
    float wgt1 = 0.f;
    if (has1) { s1 = src[e1]; t1 = tgt[e1]; r1 = etype[e1]; wgt1 = eweight[e1]; }

    // issue all 4 gathers up front
    float4 xs0 = *reinterpret_cast<const float4*>(x + (size_t)s0 * DIM + lane * BS);
    float4 xt0 = *reinterpret_cast<const float4*>(x + (size_t)t0 * DIM + lane * BS);
    float4 xs1 = *reinterpret_cast<const float4*>(x + (size_t)s1 * DIM + lane * BS);
    float4 xt1 = *reinterpret_cast<const float4*>(x + (size_t)t1 * DIM + lane * BS);

    // ---- edge 0 ----
    {
        const float* wb = g_wt + (size_t)r0 * BLK_STRIDE + lane * 4;
        float4 w0 = *reinterpret_cast<const float4*>(wb);
        float4 w1 = *reinterpret_cast<const float4*>(wb + 128);
        float4 w2 = *reinterpret_cast<const float4*>(wb + 256);
        float4 w3 = *reinterpret_cast<const float4*>(wb + 384);

        float4 m1 = block_mm(xs0, w0, w1, w2, w3);
        m1.x *= wgt0; m1.y *= wgt0; m1.z *= wgt0; m1.w *= wgt0;
        float4 m2 = block_mm(xt0, w0, w1, w2, w3);
        m2.x *= wgt0; m2.y *= wgt0; m2.z *= wgt0; m2.w *= wgt0;

        red_add_v4(out + (size_t)t0 * DIM + lane * BS, m1);
        red_add_v4(out + (size_t)s0 * DIM + lane * BS, m2);
    }

    // ---- edge 1 ----
    if (has1) {
        const float* wb = g_wt + (size_t)r1 * BLK_STRIDE + lane * 4;
        float4 w0 = *reinterpret_cast<const float4*>(wb);
        float4 w1 = *reinterpret_cast<const float4*>(wb + 128);
        float4 w2 = *reinterpret_cast<const float4*>(wb + 256);
        float4 w3 = *reinterpret_cast<const float4*>(wb + 384);

        float4 m1 = block_mm(xs1, w0, w1, w2, w3);
        m1.x *= wgt1; m1.y *= wgt1; m1.z *= wgt1; m1.w *= wgt1;
        float4 m2 = block_mm(xt1, w0, w1, w2, w3);
        m2.x *= wgt1; m2.y *= wgt1; m2.z *= wgt1; m2.w *= wgt1;

        red_add_v4(out + (size_t)t1 * DIM + lane * BS, m1);
        red_add_v4(out + (size_t)s1 * DIM + lane * BS, m2);
    }
}

extern "C" void kernel_launch(void* const* d_in, const int* in_sizes, int n_in,
                              void* d_out, int out_size)
{
    const float* x      = (const float*)d_in[0];
    const int*   mask   = (const int*)d_in[1];
    const int*   src    = (const int*)d_in[2];
    const int*   tgt    = (const int*)d_in[3];
    const int*   etype  = (const int*)d_in[4];
    const float* ew     = (const float*)d_in[5];
    const float* blocks = (const float*)d_in[6];
    float*       out    = (float*)d_out;

    int n_nodes = in_sizes[0] / DIM;
    int n_edges = in_sizes[2];
    int half = (n_edges + 1) / 2;

    // K1: out init (self-loop+mask) + weight transpose into g_wt
    {
        int total_threads = n_nodes * 32;
        int grid = (total_threads + 255) / 256;
        self_loop_kernel<<<grid, 256>>>(x, mask, blocks, out, n_nodes);
    }
    // K2: edge messages, 2 edges/warp, both directions, vectorized reductions
    {
        int total_threads = half * 32;
        int grid = (total_threads + 255) / 256;
        edge_kernel<<<grid, 256>>>(x, src, tgt, etype, ew, out, n_edges, half);
    }
}